// round 1
// baseline (speedup 1.0000x reference)
#include <cuda_runtime.h>
#include <math.h>

#define B 64
#define T 128
#define V 25
#define C 128
#define K 128
#define R 32

// ---------------- scratch (device globals; no allocations allowed) ----------
__device__ float g_xbar[B*V*C];        // mean over T of x
__device__ float g_phi [B*V*K];
__device__ float g_theta[B*V*K];
__device__ float g_Hbar[B*V*K];
__device__ float g_Atil[B*V*V*K];      // layout [b][u][v][k]  (k contiguous)
__device__ float g_gate[B*K];
__device__ float g_H[B*T*V*K];         // layout [b][t][v][k]

// ---------------- K1: xbar = mean_t x  --------------------------------------
__global__ void k1_xbar(const float* __restrict__ x) {
    int bv = blockIdx.x;               // b*V+v
    int c  = threadIdx.x;              // 0..127
    int b = bv / V, v = bv % V;
    const float* p = x + ((size_t)(b*T)*V + v)*C + c;
    float acc = 0.f;
#pragma unroll 4
    for (int t = 0; t < T; t++) acc += p[(size_t)t*V*C];
    g_xbar[bv*C + c] = acc * (1.0f/T);
}

// ---------------- K2: phi_x / theta_x / Hbar  (xbar @ W + b) ----------------
__global__ void k2_small(const float* __restrict__ pw, const float* __restrict__ pb,
                         const float* __restrict__ tw, const float* __restrict__ tb,
                         const float* __restrict__ xw, const float* __restrict__ xb2) {
    extern __shared__ float sm2[];
    float* xb_s = sm2;            // 3200
    float* W_s  = sm2 + 3200;     // 16384
    int b = blockIdx.x, tid = threadIdx.x;
    for (int lin = tid; lin < V*C; lin += 256) xb_s[lin] = g_xbar[b*V*C + lin];

    const float* Wp[3] = {pw, tw, xw};
    const float* Bp[3] = {pb, tb, xb2};
    float* Op[3];
    Op[0] = g_phi; Op[1] = g_theta; Op[2] = g_Hbar;

    for (int w = 0; w < 3; w++) {
        for (int lin = tid; lin < C*K; lin += 256) W_s[lin] = Wp[w][lin];
        __syncthreads();
        for (int task = tid; task < V*(K/4); task += 256) {
            int v  = task >> 5;
            int k4 = (task & 31) << 2;
            float4 acc = *(const float4*)&Bp[w][k4];
            for (int c = 0; c < C; c++) {
                float a = xb_s[v*C + c];
                float4 wv = *(const float4*)&W_s[c*K + k4];
                acc.x += a*wv.x; acc.y += a*wv.y; acc.z += a*wv.z; acc.w += a*wv.w;
            }
            *(float4*)&Op[w][b*V*K + v*K + k4] = acc;
        }
        __syncthreads();
    }
}

// ---------------- K3: A_tilde[b][u][v][k] = A[k,u,v] + lam*(F@kappa + b) ----
#define PAIRS_PER_BLK 32
#define FPAD 132
__global__ void k3_atilde(const float* __restrict__ A, const float* __restrict__ lam_p,
                          const float* __restrict__ kw, const float* __restrict__ kb) {
    extern __shared__ float sm3[];
    float* kap_s = sm3;                 // 16384
    float* F_s   = sm3 + C*K;           // 32*132
    int b = blockIdx.x / 20;
    int chunk = blockIdx.x % 20;
    int tid = threadIdx.x;

    for (int lin = tid; lin < K*K; lin += 256) kap_s[lin] = kw[lin];

    for (int idx = tid; idx < PAIRS_PER_BLK*K; idx += 256) {
        int p = idx >> 7, m = idx & 127;
        int pair = chunk*PAIRS_PER_BLK + p;
        float f = 0.f;
        if (pair < V*V) {
            int i = pair / V, j = pair % V;
            f = tanhf(g_phi[(b*V+i)*K + m] - g_theta[(b*V+j)*K + m]);
        }
        F_s[p*FPAD + m] = f;
    }
    __syncthreads();

    int wid = tid >> 5, lane = tid & 31;
    int k0 = wid * 16;
    int pair = chunk*PAIRS_PER_BLK + lane;
    if (pair >= V*V) return;

    float acc[16];
#pragma unroll
    for (int q = 0; q < 16; q++) acc[q] = 0.f;

    for (int m = 0; m < K; m += 4) {
        float4 f4 = *(const float4*)&F_s[lane*FPAD + m];
#pragma unroll
        for (int g = 0; g < 4; g++) {
            float4 r0 = *(const float4*)&kap_s[(m+0)*K + k0 + g*4];
            float4 r1 = *(const float4*)&kap_s[(m+1)*K + k0 + g*4];
            float4 r2 = *(const float4*)&kap_s[(m+2)*K + k0 + g*4];
            float4 r3 = *(const float4*)&kap_s[(m+3)*K + k0 + g*4];
            acc[g*4+0] += f4.x*r0.x + f4.y*r1.x + f4.z*r2.x + f4.w*r3.x;
            acc[g*4+1] += f4.x*r0.y + f4.y*r1.y + f4.z*r2.y + f4.w*r3.y;
            acc[g*4+2] += f4.x*r0.z + f4.y*r1.z + f4.z*r2.z + f4.w*r3.z;
            acc[g*4+3] += f4.x*r0.w + f4.y*r1.w + f4.z*r2.w + f4.w*r3.w;
        }
    }

    float lamv = *lam_p;
    int i = pair / V, j = pair % V;
    int outbase = ((b*V + i)*V + j)*K + k0;
#pragma unroll
    for (int g = 0; g < 4; g++) {
        float4 r;
        int kk = k0 + g*4;
        r.x = A[((kk+0)*V + i)*V + j] + lamv*(acc[g*4+0] + kb[kk+0]);
        r.y = A[((kk+1)*V + i)*V + j] + lamv*(acc[g*4+1] + kb[kk+1]);
        r.z = A[((kk+2)*V + i)*V + j] + lamv*(acc[g*4+2] + kb[kk+2]);
        r.w = A[((kk+3)*V + i)*V + j] + lamv*(acc[g*4+3] + kb[kk+3]);
        *(float4*)&g_Atil[outbase + g*4] = r;
    }
}

// ---------------- K4: gate[b][k] (Zbar -> XQ/XK -> softmax -> ca -> MLP) ----
__global__ void k4_gate(const float* __restrict__ qw, const float* __restrict__ qb,
                        const float* __restrict__ kw, const float* __restrict__ kb,
                        const float* __restrict__ c1w, const float* __restrict__ c1b,
                        const float* __restrict__ l1w, const float* __restrict__ l1b,
                        const float* __restrict__ c2w, const float* __restrict__ c2b) {
    extern __shared__ float sm4[];
    float* Hb_s = sm4;                 // 3200
    float* Zb_s = Hb_s + V*K;          // 3200
    float* XQ_s = Zb_s + V*K;          // 3200
    float* XK_s = XQ_s + V*K;          // 3200
    float* ca_s = XK_s + V*K;          // 256
    float* c1_s = ca_s + 256;          // 32

    int b = blockIdx.x, tid = threadIdx.x;
    int k = tid & 127, uh = tid >> 7;
    for (int lin = tid; lin < V*K; lin += 256) Hb_s[lin] = g_Hbar[b*V*K + lin];
    __syncthreads();

    int u_lo = uh ? 13 : 0, u_hi = uh ? 25 : 13;
    for (int u = u_lo; u < u_hi; u++) {
        float acc = 0.f;
        const float* ap = g_Atil + ((b*V + u)*V)*K + k;
#pragma unroll
        for (int v = 0; v < V; v++) acc += ap[v*K] * Hb_s[v*K + k];
        Zb_s[u*K + k] = acc;
    }
    __syncthreads();

    for (int u = u_lo; u < u_hi; u++) {
        float aq = qb[k], ak = kb[k];
        for (int m = 0; m < K; m++) {
            float z = Zb_s[u*K + m];
            aq += z * qw[m*K + k];
            ak += z * kw[m*K + k];
        }
        XQ_s[u*K + k] = aq;
        XK_s[u*K + k] = ak;
    }
    __syncthreads();

    const float inv_scale = 1.0f / sqrtf((float)T);
    float ca = 0.f;
    for (int u = u_lo; u < u_hi; u++) {
        float xq = XQ_s[u*K + k];
        float mx = -1e30f;
#pragma unroll
        for (int v = 0; v < V; v++) {
            float s = xq * XK_s[v*K + k] * inv_scale;
            mx = fmaxf(mx, s);
        }
        float den = 0.f, num = 0.f;
#pragma unroll
        for (int v = 0; v < V; v++) {
            float s = xq * XK_s[v*K + k] * inv_scale;
            float e = expf(s - mx);
            den += e;
            num += e * Hb_s[v*K + k];
        }
        ca += num / den;
    }
    ca_s[tid] = ca;
    __syncthreads();
    if (uh == 0) ca_s[k] = (ca_s[k] + ca_s[k + 128]) * (1.0f/V);
    __syncthreads();

    if (tid < R) {
        float t = c1b[tid];
        for (int kk = 0; kk < K; kk++) t += ca_s[kk] * c1w[kk*R + tid];
        // LayerNorm over R=32 within warp 0
        float mu = t;
#pragma unroll
        for (int o = 16; o > 0; o >>= 1) mu += __shfl_xor_sync(0xffffffffu, mu, o);
        mu *= (1.0f/R);
        float d = t - mu;
        float var = d*d;
#pragma unroll
        for (int o = 16; o > 0; o >>= 1) var += __shfl_xor_sync(0xffffffffu, var, o);
        var *= (1.0f/R);
        float y = d * rsqrtf(var + 1e-5f) * l1w[tid] + l1b[tid];
        c1_s[tid] = 0.5f * y * (1.0f + erff(y * 0.70710678118654752f));
    }
    __syncthreads();

    if (uh == 0) {
        float g = c2b[k];
#pragma unroll
        for (int r = 0; r < R; r++) g += c1_s[r] * c2w[r*K + k];
        g_gate[b*K + k] = 1.0f / (1.0f + expf(-g));
    }
}

// ---------------- K5: H = x @ xi_w + xi_b  (rows = B*T*V = 204800) ----------
__global__ void __launch_bounds__(256) k5_hgemm(const float* __restrict__ x,
                                                const float* __restrict__ xiw,
                                                const float* __restrict__ xib) {
    __shared__ float xs[16*132];   // [c][r], padded
    __shared__ float bs[16*128];   // [c][k]
    int tid = threadIdx.x;
    int tx = tid & 15, ty = tid >> 4;
    int row0 = blockIdx.x * 128;

    float acc[8][8];
#pragma unroll
    for (int i = 0; i < 8; i++)
#pragma unroll
        for (int j = 0; j < 8; j++) acc[i][j] = 0.f;

    for (int cc = 0; cc < C; cc += 16) {
#pragma unroll
        for (int rep = 0; rep < 8; rep++) {
            int lin = rep*256 + tid;
            int r = lin >> 4, c = lin & 15;
            xs[c*132 + r] = x[(size_t)(row0 + r)*C + cc + c];
        }
#pragma unroll
        for (int rep = 0; rep < 8; rep++) {
            int lin = rep*256 + tid;
            int c = lin >> 7, kk = lin & 127;
            bs[c*128 + kk] = xiw[(cc + c)*K + kk];
        }
        __syncthreads();
#pragma unroll
        for (int c = 0; c < 16; c++) {
            float4 a0 = *(const float4*)&xs[c*132 + ty*8];
            float4 a1 = *(const float4*)&xs[c*132 + ty*8 + 4];
            float4 b0 = *(const float4*)&bs[c*128 + tx*8];
            float4 b1 = *(const float4*)&bs[c*128 + tx*8 + 4];
            float av[8] = {a0.x,a0.y,a0.z,a0.w,a1.x,a1.y,a1.z,a1.w};
            float bv[8] = {b0.x,b0.y,b0.z,b0.w,b1.x,b1.y,b1.z,b1.w};
#pragma unroll
            for (int i = 0; i < 8; i++)
#pragma unroll
                for (int j = 0; j < 8; j++) acc[i][j] += av[i]*bv[j];
        }
        __syncthreads();
    }

    float4 bb0 = *(const float4*)&xib[tx*8];
    float4 bb1 = *(const float4*)&xib[tx*8 + 4];
    float bias[8] = {bb0.x,bb0.y,bb0.z,bb0.w,bb1.x,bb1.y,bb1.z,bb1.w};
#pragma unroll
    for (int i = 0; i < 8; i++) {
        int row = row0 + ty*8 + i;
        float4 o0, o1;
        o0.x = acc[i][0]+bias[0]; o0.y = acc[i][1]+bias[1];
        o0.z = acc[i][2]+bias[2]; o0.w = acc[i][3]+bias[3];
        o1.x = acc[i][4]+bias[4]; o1.y = acc[i][5]+bias[5];
        o1.z = acc[i][6]+bias[6]; o1.w = acc[i][7]+bias[7];
        *(float4*)&g_H[(size_t)row*K + tx*8]     = o0;
        *(float4*)&g_H[(size_t)row*K + tx*8 + 4] = o1;
    }
}

// ---------------- K6: Z_G = gate * (A_tilde . H), then LayerNorm over k -----
#define HSROW 132
#define TT 8
__global__ void __launch_bounds__(256, 1) k6_zg_ln(const float* __restrict__ l2w,
                                                   const float* __restrict__ l2b,
                                                   float* __restrict__ out) {
    extern __shared__ float sm6[];
    float* Hs   = sm6;                    // 200 * 132
    float* As   = Hs + TT*V*HSROW;        // 3200
    float* mu_s = As + V*K;               // 200
    float* rs_s = mu_s + TT*V;            // 200

    int b  = blockIdx.x >> 4;
    int tt = blockIdx.x & 15;
    int tid = threadIdx.x;
    int k = tid & 127, th = tid >> 7;

    const float gk = g_gate[b*K + k];
    int base = (b*T + tt*TT) * V * K;     // contiguous TT*V rows of K

    for (int lin = tid; lin < TT*V*K; lin += 256)
        Hs[(lin >> 7)*HSROW + (lin & 127)] = g_H[(size_t)base + lin];
    __syncthreads();

    float z[4][V];
#pragma unroll
    for (int i = 0; i < 4; i++)
#pragma unroll
        for (int u = 0; u < V; u++) z[i][u] = 0.f;

    for (int v = 0; v < V; v++) {
        const float* ap = g_Atil + (size_t)b*V*V*K + v*K;
        for (int lin = tid; lin < V*K; lin += 256)
            As[lin] = ap[(size_t)(lin >> 7)*(V*K) + (lin & 127)];
        __syncthreads();
        float h[4];
#pragma unroll
        for (int i = 0; i < 4; i++) h[i] = Hs[((th*4 + i)*V + v)*HSROW + k];
#pragma unroll
        for (int u = 0; u < V; u++) {
            float a = As[u*K + k];
#pragma unroll
            for (int i = 0; i < 4; i++) z[i][u] += a * h[i];
        }
        __syncthreads();
    }

#pragma unroll
    for (int i = 0; i < 4; i++) {
        int t = th*4 + i;
#pragma unroll
        for (int u = 0; u < V; u++) Hs[(t*V + u)*HSROW + k] = z[i][u] * gk;
    }
    __syncthreads();

    for (int p = tid; p < TT*V; p += 256) {
        float s = 0.f, s2 = 0.f;
        for (int kk = 0; kk < K; kk++) {
            float val = Hs[p*HSROW + kk];
            s += val; s2 += val*val;
        }
        float m = s * (1.0f/K);
        float var = s2 * (1.0f/K) - m*m;
        mu_s[p] = m;
        rs_s[p] = rsqrtf(var + 1e-5f);
    }
    __syncthreads();

    for (int lin = tid; lin < TT*V*K; lin += 256) {
        int r = lin >> 7, kk = lin & 127;
        float val = (Hs[r*HSROW + kk] - mu_s[r]) * rs_s[r];
        out[(size_t)base + lin] = val * l2w[kk] + l2b[kk];
    }
}

// ---------------- launch --------------------------------------------------
extern "C" void kernel_launch(void* const* d_in, const int* in_sizes, int n_in,
                              void* d_out, int out_size) {
    const float* x    = (const float*)d_in[0];
    const float* A    = (const float*)d_in[1];
    const float* lam  = (const float*)d_in[2];
    const float* phiw = (const float*)d_in[3];
    const float* phib = (const float*)d_in[4];
    const float* thw  = (const float*)d_in[5];
    const float* thb  = (const float*)d_in[6];
    const float* kapw = (const float*)d_in[7];
    const float* kapb = (const float*)d_in[8];
    const float* xiw  = (const float*)d_in[9];
    const float* xib  = (const float*)d_in[10];
    const float* qw   = (const float*)d_in[11];
    const float* qb   = (const float*)d_in[12];
    const float* kw   = (const float*)d_in[13];
    const float* kb   = (const float*)d_in[14];
    const float* c1w  = (const float*)d_in[15];
    const float* c1b  = (const float*)d_in[16];
    const float* l1w  = (const float*)d_in[17];
    const float* l1b  = (const float*)d_in[18];
    const float* c2w  = (const float*)d_in[19];
    const float* c2b  = (const float*)d_in[20];
    const float* l2w  = (const float*)d_in[21];
    const float* l2b  = (const float*)d_in[22];
    float* out = (float*)d_out;

    size_t sm2 = (size_t)(3200 + 16384) * 4;
    size_t sm3 = (size_t)(16384 + 32*FPAD) * 4;
    size_t sm4 = (size_t)(4*V*K + 256 + 32) * 4;
    size_t sm6 = (size_t)(TT*V*HSROW + V*K + 2*TT*V) * 4;

    cudaFuncSetAttribute(k2_small,  cudaFuncAttributeMaxDynamicSharedMemorySize, (int)sm2);
    cudaFuncSetAttribute(k3_atilde, cudaFuncAttributeMaxDynamicSharedMemorySize, (int)sm3);
    cudaFuncSetAttribute(k4_gate,   cudaFuncAttributeMaxDynamicSharedMemorySize, (int)sm4);
    cudaFuncSetAttribute(k6_zg_ln,  cudaFuncAttributeMaxDynamicSharedMemorySize, (int)sm6);

    k1_xbar<<<B*V, 128>>>(x);
    k2_small<<<B, 256, sm2>>>(phiw, phib, thw, thb, xiw, xib);
    k3_atilde<<<B*20, 256, sm3>>>(A, lam, kapw, kapb);
    k4_gate<<<B, 256, sm4>>>(qw, qb, kw, kb, c1w, c1b, l1w, l1b, c2w, c2b);
    k5_hgemm<<<(B*T*V)/128, 256>>>(x, xiw, xib);
    k6_zg_ln<<<B*16, 256, sm6>>>(l2w, l2b, out);
}

// round 2
// speedup vs baseline: 1.1574x; 1.1574x over previous
#include <cuda_runtime.h>
#include <math.h>

#define B 64
#define T 128
#define V 25
#define C 128
#define K 128
#define R 32

// ---------------- scratch (device globals; no allocations allowed) ----------
__device__ float g_xbar[B*V*C];        // mean over T of x
__device__ float g_phi [B*V*K];
__device__ float g_theta[B*V*K];
__device__ float g_Hbar[B*V*K];
__device__ float g_Atil[B*V*V*K];      // layout [b][u][v][k]  (k contiguous)
__device__ float g_gate[B*K];

// f32x2 packed FMA (SASS FFMA2) -- exact fp32, 2x rate
__device__ __forceinline__ unsigned long long fma2(unsigned long long a,
                                                   unsigned long long b,
                                                   unsigned long long c) {
    unsigned long long d;
    asm("fma.rn.f32x2 %0, %1, %2, %3;" : "=l"(d) : "l"(a), "l"(b), "l"(c));
    return d;
}

// ---------------- K1: xbar = mean_t x  --------------------------------------
__global__ void k1_xbar(const float* __restrict__ x) {
    int bv = blockIdx.x;               // b*V+v
    int c  = threadIdx.x;              // 0..127
    int b = bv / V, v = bv % V;
    const float* p = x + ((size_t)(b*T)*V + v)*C + c;
    float acc = 0.f;
#pragma unroll 8
    for (int t = 0; t < T; t++) acc += p[(size_t)t*V*C];
    g_xbar[bv*C + c] = acc * (1.0f/T);
}

// ---------------- K2: phi_x / theta_x / Hbar  (xbar @ W + b) ----------------
__global__ void k2_small(const float* __restrict__ pw, const float* __restrict__ pb,
                         const float* __restrict__ tw, const float* __restrict__ tb,
                         const float* __restrict__ xw, const float* __restrict__ xb2) {
    extern __shared__ float sm2[];
    float* xb_s = sm2;            // 3200
    float* W_s  = sm2 + 3200;     // 16384
    int b = blockIdx.x, tid = threadIdx.x;
    for (int lin = tid; lin < V*C; lin += 256) xb_s[lin] = g_xbar[b*V*C + lin];

    const float* Wp[3] = {pw, tw, xw};
    const float* Bp[3] = {pb, tb, xb2};
    float* Op[3];
    Op[0] = g_phi; Op[1] = g_theta; Op[2] = g_Hbar;

    for (int w = 0; w < 3; w++) {
        for (int lin = tid; lin < C*K; lin += 256) W_s[lin] = Wp[w][lin];
        __syncthreads();
        for (int task = tid; task < V*(K/4); task += 256) {
            int v  = task >> 5;
            int k4 = (task & 31) << 2;
            float4 acc = *(const float4*)&Bp[w][k4];
            for (int c = 0; c < C; c++) {
                float a = xb_s[v*C + c];
                float4 wv = *(const float4*)&W_s[c*K + k4];
                acc.x += a*wv.x; acc.y += a*wv.y; acc.z += a*wv.z; acc.w += a*wv.w;
            }
            *(float4*)&Op[w][b*V*K + v*K + k4] = acc;
        }
        __syncthreads();
    }
}

// ---------------- K3: A_tilde[b][u][v][k] = A[k,u,v] + lam*(F@kappa + b) ----
#define PAIRS_PER_BLK 32
#define FPAD 132
__global__ void k3_atilde(const float* __restrict__ A, const float* __restrict__ lam_p,
                          const float* __restrict__ kw, const float* __restrict__ kb) {
    extern __shared__ float sm3[];
    float* kap_s = sm3;                 // 16384
    float* F_s   = sm3 + C*K;           // 32*132
    int b = blockIdx.x / 20;
    int chunk = blockIdx.x % 20;
    int tid = threadIdx.x;

    for (int lin = tid; lin < K*K; lin += 256) kap_s[lin] = kw[lin];

    for (int idx = tid; idx < PAIRS_PER_BLK*K; idx += 256) {
        int p = idx >> 7, m = idx & 127;
        int pair = chunk*PAIRS_PER_BLK + p;
        float f = 0.f;
        if (pair < V*V) {
            int i = pair / V, j = pair % V;
            f = tanhf(g_phi[(b*V+i)*K + m] - g_theta[(b*V+j)*K + m]);
        }
        F_s[p*FPAD + m] = f;
    }
    __syncthreads();

    int wid = tid >> 5, lane = tid & 31;
    int k0 = wid * 16;
    int pair = chunk*PAIRS_PER_BLK + lane;
    if (pair >= V*V) return;

    float acc[16];
#pragma unroll
    for (int q = 0; q < 16; q++) acc[q] = 0.f;

    for (int m = 0; m < K; m += 4) {
        float4 f4 = *(const float4*)&F_s[lane*FPAD + m];
#pragma unroll
        for (int g = 0; g < 4; g++) {
            float4 r0 = *(const float4*)&kap_s[(m+0)*K + k0 + g*4];
            float4 r1 = *(const float4*)&kap_s[(m+1)*K + k0 + g*4];
            float4 r2 = *(const float4*)&kap_s[(m+2)*K + k0 + g*4];
            float4 r3 = *(const float4*)&kap_s[(m+3)*K + k0 + g*4];
            acc[g*4+0] += f4.x*r0.x + f4.y*r1.x + f4.z*r2.x + f4.w*r3.x;
            acc[g*4+1] += f4.x*r0.y + f4.y*r1.y + f4.z*r2.y + f4.w*r3.y;
            acc[g*4+2] += f4.x*r0.z + f4.y*r1.z + f4.z*r2.z + f4.w*r3.z;
            acc[g*4+3] += f4.x*r0.w + f4.y*r1.w + f4.z*r2.w + f4.w*r3.w;
        }
    }

    float lamv = *lam_p;
    int i = pair / V, j = pair % V;
    int outbase = ((b*V + i)*V + j)*K + k0;
#pragma unroll
    for (int g = 0; g < 4; g++) {
        float4 r;
        int kk = k0 + g*4;
        r.x = A[((kk+0)*V + i)*V + j] + lamv*(acc[g*4+0] + kb[kk+0]);
        r.y = A[((kk+1)*V + i)*V + j] + lamv*(acc[g*4+1] + kb[kk+1]);
        r.z = A[((kk+2)*V + i)*V + j] + lamv*(acc[g*4+2] + kb[kk+2]);
        r.w = A[((kk+3)*V + i)*V + j] + lamv*(acc[g*4+3] + kb[kk+3]);
        *(float4*)&g_Atil[outbase + g*4] = r;
    }
}

// ---------------- K4: gate[b][k]  (512 threads, smem-staged weights) --------
__global__ void __launch_bounds__(512) k4_gate(
        const float* __restrict__ qw, const float* __restrict__ qb,
        const float* __restrict__ kw, const float* __restrict__ kb,
        const float* __restrict__ c1w, const float* __restrict__ c1b,
        const float* __restrict__ l1w, const float* __restrict__ l1b,
        const float* __restrict__ c2w, const float* __restrict__ c2b) {
    extern __shared__ float sm4[];
    float* Hb_s = sm4;                 // 3200
    float* Zb_s = Hb_s + 3200;         // 3200
    float* XQ_s = Zb_s + 3200;         // 3200
    float* XK_s = XQ_s + 3200;         // 3200
    float* qw_s = XK_s + 3200;         // 4096
    float* kw_s = qw_s + 4096;         // 4096
    float* ca_s = kw_s + 4096;         // 512
    float* c1_s = ca_s + 512;          // 32

    int b = blockIdx.x, tid = threadIdx.x;
    int k = tid & 127, uh = tid >> 7;          // uh 0..3
    for (int lin = tid; lin < V*K; lin += 512) Hb_s[lin] = g_Hbar[b*V*K + lin];
    __syncthreads();

    int u_lo = (uh == 0) ? 0 : (7 + 6*(uh-1));
    int nu   = (uh == 0) ? 7 : 6;

    // Zbar[u,k] = sum_v Atil[k,u,v] * Hbar[v,k]
    for (int ui = 0; ui < nu; ui++) {
        int u = u_lo + ui;
        float acc = 0.f;
        const float* ap = g_Atil + ((size_t)(b*V + u)*V)*K + k;
#pragma unroll
        for (int v = 0; v < V; v++) acc += ap[v*K] * Hb_s[v*K + k];
        Zb_s[u*K + k] = acc;
    }
    __syncthreads();

    // XQ/XK = Zb @ qw/kw, weights staged in smem chunks of 32 rows
    float accq[7], acck[7];
    for (int ui = 0; ui < nu; ui++) { accq[ui] = qb[k]; acck[ui] = kb[k]; }
    for (int mc = 0; mc < K; mc += 32) {
        for (int lin = tid; lin < 32*128; lin += 512) {
            int mm = lin >> 7, kk = lin & 127;
            qw_s[lin] = qw[(mc + mm)*K + kk];
            kw_s[lin] = kw[(mc + mm)*K + kk];
        }
        __syncthreads();
        for (int ui = 0; ui < nu; ui++) {
            int u = u_lo + ui;
            float aq = accq[ui], ak = acck[ui];
#pragma unroll
            for (int mm = 0; mm < 32; mm++) {
                float z = Zb_s[u*K + mc + mm];
                aq += z * qw_s[mm*128 + k];
                ak += z * kw_s[mm*128 + k];
            }
            accq[ui] = aq; acck[ui] = ak;
        }
        __syncthreads();
    }
    for (int ui = 0; ui < nu; ui++) {
        XQ_s[(u_lo+ui)*K + k] = accq[ui];
        XK_s[(u_lo+ui)*K + k] = acck[ui];
    }
    __syncthreads();

    const float inv_scale = 1.0f / sqrtf((float)T);
    float ca = 0.f;
    for (int ui = 0; ui < nu; ui++) {
        int u = u_lo + ui;
        float xq = XQ_s[u*K + k];
        float mx = -1e30f;
#pragma unroll
        for (int v = 0; v < V; v++) {
            float s = xq * XK_s[v*K + k] * inv_scale;
            mx = fmaxf(mx, s);
        }
        float den = 0.f, num = 0.f;
#pragma unroll
        for (int v = 0; v < V; v++) {
            float s = xq * XK_s[v*K + k] * inv_scale;
            float e = expf(s - mx);
            den += e;
            num += e * Hb_s[v*K + k];
        }
        ca += num / den;
    }
    ca_s[tid] = ca;
    __syncthreads();
    if (tid < 128)
        ca_s[tid] = (ca_s[tid] + ca_s[tid+128] + ca_s[tid+256] + ca_s[tid+384]) * (1.0f/V);
    __syncthreads();

    if (tid < R) {
        float t = c1b[tid];
        for (int kk = 0; kk < K; kk++) t += ca_s[kk] * c1w[kk*R + tid];
        float mu = t;
#pragma unroll
        for (int o = 16; o > 0; o >>= 1) mu += __shfl_xor_sync(0xffffffffu, mu, o);
        mu *= (1.0f/R);
        float d = t - mu;
        float var = d*d;
#pragma unroll
        for (int o = 16; o > 0; o >>= 1) var += __shfl_xor_sync(0xffffffffu, var, o);
        var *= (1.0f/R);
        float y = d * rsqrtf(var + 1e-5f) * l1w[tid] + l1b[tid];
        c1_s[tid] = 0.5f * y * (1.0f + erff(y * 0.70710678118654752f));
    }
    __syncthreads();

    if (tid < 128) {
        float g = c2b[k];
#pragma unroll
        for (int r = 0; r < R; r++) g += c1_s[r] * c2w[r*K + k];
        g_gate[b*K + k] = 1.0f / (1.0f + expf(-g));
    }
}

// ---------------- K56: fused H-GEMM (f32x2) + gated GCN + LayerNorm ---------
#define TT 8
#define HSROW 132
__global__ void __launch_bounds__(256, 1) k56_fused(
        const float* __restrict__ x,
        const float* __restrict__ xiw, const float* __restrict__ xib,
        const float* __restrict__ l2w, const float* __restrict__ l2b,
        float* __restrict__ out) {
    extern __shared__ float sm6[];
    float* Hs   = sm6;                    // 200*132 = 26400
    float* xs2  = Hs  + TT*V*HSROW;       // 200*32  = 6400 (x dup-packed)
    float* ws   = xs2 + TT*V*32;          // 16*128  = 2048
    float* As   = ws  + 16*128;           // 25*128  = 3200
    float* mu_s = As  + V*K;              // 200
    float* rs_s = mu_s + TT*V;            // 200

    int b  = blockIdx.x >> 4;
    int tt = blockIdx.x & 15;
    int tid  = threadIdx.x;
    int wid  = tid >> 5, lane = tid & 31;

    // ---------- Phase A: H tile [200 x 128] = x_tile @ xi_w + b (FFMA2) -----
    const size_t xbase = ((size_t)(b*T + tt*TT))*V*C;  // 200 contiguous rows

    unsigned long long acc[V][2];
#pragma unroll
    for (int v = 0; v < V; v++) { acc[v][0] = 0ull; acc[v][1] = 0ull; }

    for (int cc = 0; cc < C; cc += 16) {
        // x chunk, each scalar duplicated -> LDS.64 broadcast yields (x,x)
        for (int lin = tid; lin < 200*16; lin += 256) {
            int r = lin >> 4, c = lin & 15;
            float vx = x[xbase + (size_t)r*C + cc + c];
            xs2[r*32 + 2*c]     = vx;
            xs2[r*32 + 2*c + 1] = vx;
        }
        for (int lin = tid; lin < 16*128; lin += 256) {
            int c = lin >> 7, kk = lin & 127;
            ws[lin] = xiw[(cc + c)*K + kk];
        }
        __syncthreads();

        const float* xrow0 = &xs2[wid*V*32];
        for (int c = 0; c < 16; c++) {
            const unsigned long long* wp =
                (const unsigned long long*)&ws[c*128 + lane*4];
            unsigned long long w01 = wp[0], w23 = wp[1];
#pragma unroll
            for (int v = 0; v < V; v++) {
                unsigned long long xv2 =
                    *(const unsigned long long*)&xrow0[v*32 + 2*c];
                acc[v][0] = fma2(xv2, w01, acc[v][0]);
                acc[v][1] = fma2(xv2, w23, acc[v][1]);
            }
        }
        __syncthreads();
    }

    // write H tile (+bias) to smem; warp wid owns t=wid rows
    float4 bias4 = *(const float4*)&xib[lane*4];
#pragma unroll
    for (int v = 0; v < V; v++) {
        float lo0, hi0, lo1, hi1;
        asm("mov.b64 {%0,%1}, %2;" : "=f"(lo0), "=f"(hi0) : "l"(acc[v][0]));
        asm("mov.b64 {%0,%1}, %2;" : "=f"(lo1), "=f"(hi1) : "l"(acc[v][1]));
        float4 o;
        o.x = lo0 + bias4.x; o.y = hi0 + bias4.y;
        o.z = lo1 + bias4.z; o.w = hi1 + bias4.w;
        *(float4*)&Hs[(wid*V + v)*HSROW + lane*4] = o;
    }

    // ---------- Phase B: Z = gate * (A_tilde . H), LayerNorm over k ----------
    int k = tid & 127, th = tid >> 7;          // th handles 4 t values
    const float gk = g_gate[b*K + k];

    float z[4][V];
#pragma unroll
    for (int i = 0; i < 4; i++)
#pragma unroll
        for (int u = 0; u < V; u++) z[i][u] = 0.f;

    for (int v = 0; v < V; v++) {
        const float* ap = g_Atil + (size_t)b*V*V*K + v*K;
        for (int lin = tid; lin < V*K; lin += 256)
            As[lin] = ap[(size_t)(lin >> 7)*(V*K) + (lin & 127)];
        __syncthreads();
        float h[4];
#pragma unroll
        for (int i = 0; i < 4; i++) h[i] = Hs[((th*4 + i)*V + v)*HSROW + k];
#pragma unroll
        for (int u = 0; u < V; u++) {
            float a = As[u*K + k];
#pragma unroll
            for (int i = 0; i < 4; i++) z[i][u] += a * h[i];
        }
        __syncthreads();
    }

#pragma unroll
    for (int i = 0; i < 4; i++) {
        int t = th*4 + i;
#pragma unroll
        for (int u = 0; u < V; u++) Hs[(t*V + u)*HSROW + k] = z[i][u] * gk;
    }
    __syncthreads();

    for (int p = tid; p < TT*V; p += 256) {
        float s = 0.f, s2 = 0.f;
        for (int kk = 0; kk < K; kk++) {
            float val = Hs[p*HSROW + kk];
            s += val; s2 += val*val;
        }
        float m = s * (1.0f/K);
        float var = s2 * (1.0f/K) - m*m;
        mu_s[p] = m;
        rs_s[p] = rsqrtf(var + 1e-5f);
    }
    __syncthreads();

    const size_t obase = ((size_t)(b*T + tt*TT))*V*K;
    for (int lin = tid; lin < TT*V*K; lin += 256) {
        int r = lin >> 7, kk = lin & 127;
        float val = (Hs[r*HSROW + kk] - mu_s[r]) * rs_s[r];
        out[obase + lin] = val * l2w[kk] + l2b[kk];
    }
}

// ---------------- launch --------------------------------------------------
extern "C" void kernel_launch(void* const* d_in, const int* in_sizes, int n_in,
                              void* d_out, int out_size) {
    const float* x    = (const float*)d_in[0];
    const float* A    = (const float*)d_in[1];
    const float* lam  = (const float*)d_in[2];
    const float* phiw = (const float*)d_in[3];
    const float* phib = (const float*)d_in[4];
    const float* thw  = (const float*)d_in[5];
    const float* thb  = (const float*)d_in[6];
    const float* kapw = (const float*)d_in[7];
    const float* kapb = (const float*)d_in[8];
    const float* xiw  = (const float*)d_in[9];
    const float* xib  = (const float*)d_in[10];
    const float* qw   = (const float*)d_in[11];
    const float* qb   = (const float*)d_in[12];
    const float* kw   = (const float*)d_in[13];
    const float* kb   = (const float*)d_in[14];
    const float* c1w  = (const float*)d_in[15];
    const float* c1b  = (const float*)d_in[16];
    const float* l1w  = (const float*)d_in[17];
    const float* l1b  = (const float*)d_in[18];
    const float* c2w  = (const float*)d_in[19];
    const float* c2b  = (const float*)d_in[20];
    const float* l2w  = (const float*)d_in[21];
    const float* l2b  = (const float*)d_in[22];
    float* out = (float*)d_out;

    size_t sm2  = (size_t)(3200 + 16384) * 4;
    size_t sm3  = (size_t)(16384 + 32*FPAD) * 4;
    size_t sm4  = (size_t)(4*3200 + 2*4096 + 512 + 32) * 4;
    size_t sm56 = (size_t)(TT*V*HSROW + TT*V*32 + 16*128 + V*K + 2*TT*V) * 4;

    cudaFuncSetAttribute(k2_small,   cudaFuncAttributeMaxDynamicSharedMemorySize, (int)sm2);
    cudaFuncSetAttribute(k3_atilde,  cudaFuncAttributeMaxDynamicSharedMemorySize, (int)sm3);
    cudaFuncSetAttribute(k4_gate,    cudaFuncAttributeMaxDynamicSharedMemorySize, (int)sm4);
    cudaFuncSetAttribute(k56_fused,  cudaFuncAttributeMaxDynamicSharedMemorySize, (int)sm56);

    k1_xbar<<<B*V, 128>>>(x);
    k2_small<<<B, 256, sm2>>>(phiw, phib, thw, thb, xiw, xib);
    k3_atilde<<<B*20, 256, sm3>>>(A, lam, kapw, kapb);
    k4_gate<<<B, 512, sm4>>>(qw, qb, kw, kb, c1w, c1b, l1w, l1b, c2w, c2b);
    k56_fused<<<B*16, 256, sm56>>>(x, xiw, xib, l2w, l2b, out);
}